// round 3
// baseline (speedup 1.0000x reference)
#include <cuda_runtime.h>
#include <cuda_bf16.h>
#include <cstdint>

// Problem constants
#define BATCH 4
#define HEADS 16
#define SEQ   2048
#define HDIM  64
#define DMODEL 1024
#define LN_EPS 1e-5f

// Attention tiling
#define BM 64
#define BN 64
#define NTILES (SEQ / BN)

// Strides (floats): 68 = 272B = 17*16B -> 16B aligned rows, and rows advance
// 4 banks (68 mod 32 = 4) so every LDSM 8-address phase and every fragment
// pattern is bank-conflict-free.
#define LQ  68
#define LKP 68
#define LVT 68
#define ATT_SMEM_FLOATS (64*LQ + 64*LKP + 64*LVT)
#define ATT_SMEM_BYTES  (ATT_SMEM_FLOATS * 4)

// Scratch: attention output [B, N, D] (heads re-interleaved)
__device__ float g_attn[(size_t)BATCH * SEQ * DMODEL];

// ---- helpers --------------------------------------------------------------
__device__ __forceinline__ float tf(float x) {            // round-to-nearest tf32
    uint32_t u;
    asm("cvt.rna.tf32.f32 %0, %1;" : "=r"(u) : "f"(x));
    return __uint_as_float(u);
}
__device__ __forceinline__ uint32_t smaddr(const void* p) {
    return (uint32_t)__cvta_generic_to_shared(p);
}
__device__ __forceinline__ void ldsm4(uint32_t& r0, uint32_t& r1,
                                      uint32_t& r2, uint32_t& r3, uint32_t a) {
    asm volatile("ldmatrix.sync.aligned.m8n8.x4.shared.b16 {%0,%1,%2,%3}, [%4];"
                 : "=r"(r0), "=r"(r1), "=r"(r2), "=r"(r3) : "r"(a));
}
__device__ __forceinline__ void mma_tf32(float c[4],
                                         uint32_t a0, uint32_t a1, uint32_t a2, uint32_t a3,
                                         uint32_t b0, uint32_t b1) {
    asm volatile(
        "mma.sync.aligned.m16n8k8.row.col.f32.tf32.tf32.f32 "
        "{%0,%1,%2,%3}, {%4,%5,%6,%7}, {%8,%9}, {%0,%1,%2,%3};\n"
        : "+f"(c[0]), "+f"(c[1]), "+f"(c[2]), "+f"(c[3])
        : "r"(a0), "r"(a1), "r"(a2), "r"(a3), "r"(b0), "r"(b1));
}

// ---------------------------------------------------------------------------
// Kernel 1: flash attention, tf32 tensor cores + ldmatrix fragment loads.
// grid (SEQ/BM, B*H), block 128 (4 warps). Warp w owns 16 query rows.
// ---------------------------------------------------------------------------
__global__ void __launch_bounds__(128)
attn_kernel(const float* __restrict__ q,
            const float* __restrict__ k,
            const float* __restrict__ v)
{
    extern __shared__ float sm[];
    float* Qs  = sm;                       // [64][LQ]
    float* KPs = sm + 64 * LQ;             // [64][LKP] K tile, then P tile
    float* Vt  = sm + 64 * (LQ + LKP);     // [64][LVT] rows=dim, cols=key

    const int bh = blockIdx.y;
    const int b  = bh >> 4;
    const int h  = bh & 15;
    const int qt = blockIdx.x;
    const int tid  = threadIdx.x;
    const int lane = tid & 31;
    const int w    = tid >> 5;
    const int g    = lane >> 2;   // fragment row
    const int t    = lane & 3;    // fragment col
    const int m0   = w * 16;

    // ldmatrix per-thread address decomposition
    const int mi = lane >> 3;     // matrix index 0..3
    const int rs = lane & 7;      // row-in-matrix

    // A-pattern base (Q and P): row = m0 + rs + ((mi&1)<<3), col = ((mi>>1)<<2)
    const uint32_t aQbase = smaddr(Qs  + (m0 + rs + ((mi & 1) << 3)) * LQ  + ((mi >> 1) << 2));
    const uint32_t aPbase = smaddr(KPs + (m0 + rs + ((mi & 1) << 3)) * LKP + ((mi >> 1) << 2));
    // B-pattern base (K and Vt): row = rs + ((mi>>1)<<3), col = ((mi&1)<<2)
    const uint32_t bKbase = smaddr(KPs + (rs + ((mi >> 1) << 3)) * LKP + ((mi & 1) << 2));
    const uint32_t bVbase = smaddr(Vt  + (rs + ((mi >> 1) << 3)) * LVT + ((mi & 1) << 2));

    const float scale = 0.125f;

    // Load Q tile (scale + tf32 round), coalesced
    const float* qb = q + ((size_t)(b * SEQ + qt * BM)) * DMODEL + h * HDIM;
    #pragma unroll
    for (int i = tid; i < 64 * 16; i += 128) {
        int r = i >> 4, c = i & 15;
        float4 x = *reinterpret_cast<const float4*>(qb + (size_t)r * DMODEL + c * 4);
        float4 y;
        y.x = tf(x.x * scale); y.y = tf(x.y * scale);
        y.z = tf(x.z * scale); y.w = tf(x.w * scale);
        *reinterpret_cast<float4*>(Qs + r * LQ + c * 4) = y;
    }

    float o[8][4];
    #pragma unroll
    for (int n = 0; n < 8; n++)
        #pragma unroll
        for (int j = 0; j < 4; j++) o[n][j] = 0.0f;
    float mrow[2] = {-1e30f, -1e30f};
    float lrow[2] = {0.0f, 0.0f};

    const float* kb0 = k + ((size_t)b * SEQ) * DMODEL + h * HDIM;
    const float* vb0 = v + ((size_t)b * SEQ) * DMODEL + h * HDIM;

    for (int ti = 0; ti < NTILES; ti++) {
        __syncthreads();   // previous tile's P/V consumption complete
        const float* kb = kb0 + (size_t)(ti * BN) * DMODEL;
        const float* vb = vb0 + (size_t)(ti * BN) * DMODEL;

        // K: row-major (coalesced loads)
        #pragma unroll
        for (int i = tid; i < 64 * 16; i += 128) {
            int r = i >> 4, c = i & 15;
            float4 xk = *reinterpret_cast<const float4*>(kb + (size_t)r * DMODEL + c * 4);
            float4 yk;
            yk.x = tf(xk.x); yk.y = tf(xk.y); yk.z = tf(xk.z); yk.w = tf(xk.w);
            *reinterpret_cast<float4*>(KPs + r * LKP + c * 4) = yk;
        }
        // V: transposed into Vt[dim][key]; lane->key mapping keeps the 4
        // scalar STS per thread conflict-free (banks = 16c+4j+r, r distinct).
        #pragma unroll
        for (int i = tid; i < 64 * 16; i += 128) {
            int r = i & 63, c = i >> 6;
            float4 xv = *reinterpret_cast<const float4*>(vb + (size_t)r * DMODEL + c * 4);
            Vt[(c * 4 + 0) * LVT + r] = tf(xv.x);
            Vt[(c * 4 + 1) * LVT + r] = tf(xv.y);
            Vt[(c * 4 + 2) * LVT + r] = tf(xv.z);
            Vt[(c * 4 + 3) * LVT + r] = tf(xv.w);
        }
        __syncthreads();

        // ---- S = Q K^T -----------------------------------------------------
        float s[8][4];
        #pragma unroll
        for (int n = 0; n < 8; n++)
            #pragma unroll
            for (int j = 0; j < 4; j++) s[n][j] = 0.0f;

        #pragma unroll
        for (int ks = 0; ks < 8; ks++) {
            uint32_t a0, a1, a2, a3;
            ldsm4(a0, a1, a2, a3, aQbase + ks * 32);
            #pragma unroll
            for (int np = 0; np < 4; np++) {
                uint32_t b0e, b1e, b0o, b1o;
                ldsm4(b0e, b1e, b0o, b1o, bKbase + np * (16 * LKP * 4) + ks * 32);
                mma_tf32(s[2 * np],     a0, a1, a2, a3, b0e, b1e);
                mma_tf32(s[2 * np + 1], a0, a1, a2, a3, b0o, b1o);
            }
        }
        __syncthreads();   // all warps done reading K; KPs becomes P

        // ---- online softmax; write P (tf32) into KPs -----------------------
        #pragma unroll
        for (int slot = 0; slot < 2; slot++) {
            const int c0 = slot * 2, c1 = slot * 2 + 1;
            float rmax = -1e30f;
            #pragma unroll
            for (int n = 0; n < 8; n++)
                rmax = fmaxf(rmax, fmaxf(s[n][c0], s[n][c1]));
            rmax = fmaxf(rmax, __shfl_xor_sync(0xffffffffu, rmax, 1, 4));
            rmax = fmaxf(rmax, __shfl_xor_sync(0xffffffffu, rmax, 2, 4));
            float mnew = fmaxf(mrow[slot], rmax);
            float corr = __expf(mrow[slot] - mnew);
            float psum = 0.0f;
            const int prow = (m0 + g + slot * 8) * LKP;
            #pragma unroll
            for (int n = 0; n < 8; n++) {
                float p0 = __expf(s[n][c0] - mnew);
                float p1 = __expf(s[n][c1] - mnew);
                psum += p0 + p1;
                *reinterpret_cast<float2*>(KPs + prow + n * 8 + 2 * t) =
                    make_float2(tf(p0), tf(p1));
            }
            psum += __shfl_xor_sync(0xffffffffu, psum, 1, 4);
            psum += __shfl_xor_sync(0xffffffffu, psum, 2, 4);
            lrow[slot] = lrow[slot] * corr + psum;
            mrow[slot] = mnew;
            #pragma unroll
            for (int n = 0; n < 8; n++) { o[n][c0] *= corr; o[n][c1] *= corr; }
        }
        __syncthreads();

        // ---- O += P V ------------------------------------------------------
        #pragma unroll
        for (int ks = 0; ks < 8; ks++) {
            uint32_t a0, a1, a2, a3;
            ldsm4(a0, a1, a2, a3, aPbase + ks * 32);
            #pragma unroll
            for (int np = 0; np < 4; np++) {
                uint32_t b0e, b1e, b0o, b1o;
                ldsm4(b0e, b1e, b0o, b1o, bVbase + np * (16 * LVT * 4) + ks * 32);
                mma_tf32(o[2 * np],     a0, a1, a2, a3, b0e, b1e);
                mma_tf32(o[2 * np + 1], a0, a1, a2, a3, b0o, b1o);
            }
        }
    }

    // Epilogue: normalize, write scratch
    float inv0 = 1.0f / lrow[0];
    float inv1 = 1.0f / lrow[1];
    float* ob = g_attn + ((size_t)(b * SEQ + qt * BM + m0)) * DMODEL + h * HDIM;
    #pragma unroll
    for (int n = 0; n < 8; n++) {
        *reinterpret_cast<float2*>(ob + (size_t)g * DMODEL + n * 8 + 2 * t) =
            make_float2(o[n][0] * inv0, o[n][1] * inv0);
        *reinterpret_cast<float2*>(ob + (size_t)(g + 8) * DMODEL + n * 8 + 2 * t) =
            make_float2(o[n][2] * inv1, o[n][3] * inv1);
    }
}

// ---------------------------------------------------------------------------
// Kernel 2: projection out = X @ W^T, tf32 + ldmatrix.
// Tile 128(M) x 64(N), Kchunk 32. Block 256 (8 warps, m16 each).
// Stride 36 floats = 144B (16B aligned), 36 mod 32 = 4 -> conflict-free.
// ---------------------------------------------------------------------------
#define LX 36
#define LW 36

__global__ void __launch_bounds__(256)
proj_kernel(const float* __restrict__ W, float* __restrict__ out)
{
    __shared__ float Xs[128 * LX];
    __shared__ float Ws[64 * LW];

    const int tid  = threadIdx.x;
    const int lane = tid & 31;
    const int w    = tid >> 5;
    const int g    = lane >> 2;
    const int t    = lane & 3;
    const int m0   = w * 16;
    const int mi   = lane >> 3;
    const int rs   = lane & 7;
    const int rowBase = blockIdx.y * 128;
    const int colBase = blockIdx.x * 64;

    const uint32_t aXbase = smaddr(Xs + (m0 + rs + ((mi & 1) << 3)) * LX + ((mi >> 1) << 2));
    const uint32_t bWbase = smaddr(Ws + (rs + ((mi >> 1) << 3)) * LW + ((mi & 1) << 2));

    float acc[8][4];
    #pragma unroll
    for (int n = 0; n < 8; n++)
        #pragma unroll
        for (int j = 0; j < 4; j++) acc[n][j] = 0.0f;

    for (int kt = 0; kt < DMODEL / 32; kt++) {
        #pragma unroll
        for (int i = tid; i < 128 * 8; i += 256) {
            int r = i >> 3, c = i & 7;
            float4 x = *reinterpret_cast<const float4*>(
                g_attn + (size_t)(rowBase + r) * DMODEL + kt * 32 + c * 4);
            float4 y;
            y.x = tf(x.x); y.y = tf(x.y); y.z = tf(x.z); y.w = tf(x.w);
            *reinterpret_cast<float4*>(Xs + r * LX + c * 4) = y;
        }
        #pragma unroll
        for (int i = tid; i < 64 * 8; i += 256) {
            int r = i >> 3, c = i & 7;
            float4 x = *reinterpret_cast<const float4*>(
                W + (size_t)(colBase + r) * DMODEL + kt * 32 + c * 4);
            float4 y;
            y.x = tf(x.x); y.y = tf(x.y); y.z = tf(x.z); y.w = tf(x.w);
            *reinterpret_cast<float4*>(Ws + r * LW + c * 4) = y;
        }
        __syncthreads();

        #pragma unroll
        for (int ks = 0; ks < 4; ks++) {
            uint32_t a0, a1, a2, a3;
            ldsm4(a0, a1, a2, a3, aXbase + ks * 32);
            #pragma unroll
            for (int np = 0; np < 4; np++) {
                uint32_t b0e, b1e, b0o, b1o;
                ldsm4(b0e, b1e, b0o, b1o, bWbase + np * (16 * LW * 4) + ks * 32);
                mma_tf32(acc[2 * np],     a0, a1, a2, a3, b0e, b1e);
                mma_tf32(acc[2 * np + 1], a0, a1, a2, a3, b0o, b1o);
            }
        }
        __syncthreads();
    }

    float* ob = out + (size_t)(rowBase + m0) * DMODEL + colBase;
    #pragma unroll
    for (int n = 0; n < 8; n++) {
        *reinterpret_cast<float2*>(ob + (size_t)g * DMODEL + n * 8 + 2 * t) =
            make_float2(acc[n][0], acc[n][1]);
        *reinterpret_cast<float2*>(ob + (size_t)(g + 8) * DMODEL + n * 8 + 2 * t) =
            make_float2(acc[n][2], acc[n][3]);
    }
}

// ---------------------------------------------------------------------------
// Kernel 3: in-place row LayerNorm (bias-free), row = 1024 floats.
// ---------------------------------------------------------------------------
__global__ void __launch_bounds__(256)
ln_kernel(float* __restrict__ out, const float* __restrict__ g)
{
    const int row = blockIdx.x;
    float* p = out + (size_t)row * DMODEL;
    const int tid = threadIdx.x;

    float4 x = reinterpret_cast<float4*>(p)[tid];
    float s  = x.x + x.y + x.z + x.w;
    float ss = x.x * x.x + x.y * x.y + x.z * x.z + x.w * x.w;

    #pragma unroll
    for (int off = 16; off > 0; off >>= 1) {
        s  += __shfl_xor_sync(0xffffffffu, s,  off);
        ss += __shfl_xor_sync(0xffffffffu, ss, off);
    }
    __shared__ float sbuf[8], ssbuf[8];
    if ((tid & 31) == 0) { sbuf[tid >> 5] = s; ssbuf[tid >> 5] = ss; }
    __syncthreads();
    s = 0.0f; ss = 0.0f;
    #pragma unroll
    for (int i = 0; i < 8; i++) { s += sbuf[i]; ss += ssbuf[i]; }

    const float mean = s * (1.0f / DMODEL);
    const float var  = ss * (1.0f / DMODEL) - mean * mean;
    const float rstd = rsqrtf(var + LN_EPS);

    float4 gv = reinterpret_cast<const float4*>(g)[tid];
    x.x = (x.x - mean) * rstd * gv.x;
    x.y = (x.y - mean) * rstd * gv.y;
    x.z = (x.z - mean) * rstd * gv.z;
    x.w = (x.w - mean) * rstd * gv.w;
    reinterpret_cast<float4*>(p)[tid] = x;
}

// ---------------------------------------------------------------------------
extern "C" void kernel_launch(void* const* d_in, const int* in_sizes, int n_in,
                              void* d_out, int out_size)
{
    const float* q  = (const float*)d_in[0];
    const float* k  = (const float*)d_in[1];
    const float* v  = (const float*)d_in[2];
    const float* W  = (const float*)d_in[3];
    const float* g  = (const float*)d_in[4];
    float* out = (float*)d_out;

    cudaFuncSetAttribute(attn_kernel,
                         cudaFuncAttributeMaxDynamicSharedMemorySize, ATT_SMEM_BYTES);

    dim3 agrid(SEQ / BM, BATCH * HEADS);
    attn_kernel<<<agrid, 128, ATT_SMEM_BYTES>>>(q, k, v);

    dim3 pgrid(DMODEL / 64, BATCH * SEQ / 128);
    proj_kernel<<<pgrid, 256>>>(W, out);

    ln_kernel<<<BATCH * SEQ, 256>>>(out, g);
}

// round 4
// speedup vs baseline: 1.4972x; 1.4972x over previous
#include <cuda_runtime.h>
#include <cuda_bf16.h>
#include <cstdint>

// Problem constants
#define BATCH 4
#define HEADS 16
#define SEQ   2048
#define HDIM  64
#define DMODEL 1024
#define LN_EPS 1e-5f

// Attention tiling: BM=128 rows per CTA, 4 warps, m32 per warp. BN=64 keys.
#define BM 128
#define BN 64
#define NTILES (SEQ / BN)

// Stride 68 floats = 272B (16B-aligned rows), 68 mod 32 = 4 banks advance:
// all LDSM phases + float4 fills conflict-free.
#define LS 68
#define ATT_SMEM_FLOATS ((BM + BM + BN) * LS)   // Qs[128] + KP[128] + Vt[64]
#define ATT_SMEM_BYTES  (ATT_SMEM_FLOATS * 4)

// Scratch
__device__ float g_attn[(size_t)BATCH * SEQ * DMODEL];          // [b,n,hd]
__device__ float g_vt  [(size_t)BATCH * DMODEL * SEQ];          // [b,hd,n] tf32

// ---- helpers --------------------------------------------------------------
__device__ __forceinline__ float tf(float x) {            // round-to-nearest tf32
    uint32_t u;
    asm("cvt.rna.tf32.f32 %0, %1;" : "=r"(u) : "f"(x));
    return __uint_as_float(u);
}
__device__ __forceinline__ uint32_t smaddr(const void* p) {
    return (uint32_t)__cvta_generic_to_shared(p);
}
__device__ __forceinline__ void ldsm4(uint32_t& r0, uint32_t& r1,
                                      uint32_t& r2, uint32_t& r3, uint32_t a) {
    asm volatile("ldmatrix.sync.aligned.m8n8.x4.shared.b16 {%0,%1,%2,%3}, [%4];"
                 : "=r"(r0), "=r"(r1), "=r"(r2), "=r"(r3) : "r"(a));
}
__device__ __forceinline__ void mma_tf32(float c[4],
                                         uint32_t a0, uint32_t a1, uint32_t a2, uint32_t a3,
                                         uint32_t b0, uint32_t b1) {
    asm volatile(
        "mma.sync.aligned.m16n8k8.row.col.f32.tf32.tf32.f32 "
        "{%0,%1,%2,%3}, {%4,%5,%6,%7}, {%8,%9}, {%0,%1,%2,%3};\n"
        : "+f"(c[0]), "+f"(c[1]), "+f"(c[2]), "+f"(c[3])
        : "r"(a0), "r"(a1), "r"(a2), "r"(a3), "r"(b0), "r"(b1));
}

// ---------------------------------------------------------------------------
// Kernel 0: V transpose + tf32 round.  g_vt[b, hd, n] = tf(v[b, n, hd])
// grid (SEQ/32, DMODEL/32, BATCH), block 256 (32x8), smem 32x33 tile.
// ---------------------------------------------------------------------------
__global__ void __launch_bounds__(256)
vt_kernel(const float* __restrict__ v)
{
    __shared__ float tile[32][33];
    const int b   = blockIdx.z;
    const int n0  = blockIdx.x * 32;
    const int hd0 = blockIdx.y * 32;
    const int tx  = threadIdx.x & 31;
    const int ty  = threadIdx.x >> 5;      // 0..7

    #pragma unroll
    for (int r = 0; r < 4; r++) {
        int n = n0 + ty + r * 8;
        tile[ty + r * 8][tx] = tf(v[((size_t)(b * SEQ + n)) * DMODEL + hd0 + tx]);
    }
    __syncthreads();
    #pragma unroll
    for (int r = 0; r < 4; r++) {
        int hd = hd0 + ty + r * 8;
        g_vt[((size_t)(b * DMODEL + hd)) * SEQ + n0 + tx] = tile[tx][ty + r * 8];
    }
}

// ---------------------------------------------------------------------------
// Kernel 1: flash attention. grid (SEQ/BM, B*H), block 128 (4 warps, m32 each)
// ---------------------------------------------------------------------------
__global__ void __launch_bounds__(128)
attn_kernel(const float* __restrict__ q,
            const float* __restrict__ k)
{
    extern __shared__ float sm[];
    float* Qs  = sm;                 // [128][LS]
    float* KPs = sm + BM * LS;       // [128][LS]: K in rows 0..63, P in 0..127
    float* Vs  = sm + 2 * BM * LS;   // [64][LS]: row=dim, col=key (from g_vt)

    const int bh = blockIdx.y;
    const int b  = bh >> 4;
    const int h  = bh & 15;
    const int qt = blockIdx.x;
    const int tid  = threadIdx.x;
    const int lane = tid & 31;
    const int w    = tid >> 5;
    const int g    = lane >> 2;
    const int t    = lane & 3;
    const int m0   = w * 32;

    const int mi = lane >> 3;
    const int rs = lane & 7;

    const uint32_t aQbase = smaddr(Qs  + (m0 + rs + ((mi & 1) << 3)) * LS + ((mi >> 1) << 2));
    const uint32_t aPbase = smaddr(KPs + (m0 + rs + ((mi & 1) << 3)) * LS + ((mi >> 1) << 2));
    const uint32_t bKbase = smaddr(KPs + (rs + ((mi >> 1) << 3)) * LS + ((mi & 1) << 2));
    const uint32_t bVbase = smaddr(Vs  + (rs + ((mi >> 1) << 3)) * LS + ((mi & 1) << 2));

    const float scale = 0.125f;

    // Load Q tile (scale + tf32), coalesced
    const float* qb = q + ((size_t)(b * SEQ + qt * BM)) * DMODEL + h * HDIM;
    #pragma unroll
    for (int i = tid; i < BM * 16; i += 128) {
        int r = i >> 4, c = i & 15;
        float4 x = *reinterpret_cast<const float4*>(qb + (size_t)r * DMODEL + c * 4);
        float4 y;
        y.x = tf(x.x * scale); y.y = tf(x.y * scale);
        y.z = tf(x.z * scale); y.w = tf(x.w * scale);
        *reinterpret_cast<float4*>(Qs + r * LS + c * 4) = y;
    }

    float o[2][8][4];
    #pragma unroll
    for (int hh = 0; hh < 2; hh++)
        #pragma unroll
        for (int n = 0; n < 8; n++)
            #pragma unroll
            for (int j = 0; j < 4; j++) o[hh][n][j] = 0.0f;
    float mrow[4] = {-1e30f, -1e30f, -1e30f, -1e30f};
    float lrow[4] = {0.0f, 0.0f, 0.0f, 0.0f};

    const float* kb0 = k + ((size_t)b * SEQ) * DMODEL + h * HDIM;
    const float* vtb = g_vt + ((size_t)(b * DMODEL + h * HDIM)) * SEQ;

    for (int ti = 0; ti < NTILES; ti++) {
        __syncthreads();   // prior tile fully consumed
        // K fill (coalesced, tf32)
        const float* kb = kb0 + (size_t)(ti * BN) * DMODEL;
        #pragma unroll
        for (int i = tid; i < BN * 16; i += 128) {
            int r = i >> 4, c = i & 15;
            float4 x = *reinterpret_cast<const float4*>(kb + (size_t)r * DMODEL + c * 4);
            float4 y;
            y.x = tf(x.x); y.y = tf(x.y); y.z = tf(x.z); y.w = tf(x.w);
            *reinterpret_cast<float4*>(KPs + r * LS + c * 4) = y;
        }
        // Vt fill (coalesced rows of g_vt, already tf32)
        #pragma unroll
        for (int i = tid; i < BN * 16; i += 128) {
            int r = i >> 4, c = i & 15;   // r = dim, c*4 = key offset
            float4 x = *reinterpret_cast<const float4*>(vtb + (size_t)r * SEQ + ti * BN + c * 4);
            *reinterpret_cast<float4*>(Vs + r * LS + c * 4) = x;
        }
        __syncthreads();

        // ---- S = Q K^T (two m16 halves share B-frags) ----------------------
        float s[2][8][4];
        #pragma unroll
        for (int hh = 0; hh < 2; hh++)
            #pragma unroll
            for (int n = 0; n < 8; n++)
                #pragma unroll
                for (int j = 0; j < 4; j++) s[hh][n][j] = 0.0f;

        #pragma unroll
        for (int ks = 0; ks < 8; ks++) {
            uint32_t bb[8][2];
            #pragma unroll
            for (int np = 0; np < 4; np++)
                ldsm4(bb[2 * np][0], bb[2 * np][1], bb[2 * np + 1][0], bb[2 * np + 1][1],
                      bKbase + np * (16 * LS * 4) + ks * 32);
            #pragma unroll
            for (int hh = 0; hh < 2; hh++) {
                uint32_t a0, a1, a2, a3;
                ldsm4(a0, a1, a2, a3, aQbase + hh * (16 * LS * 4) + ks * 32);
                #pragma unroll
                for (int n = 0; n < 8; n++)
                    mma_tf32(s[hh][n], a0, a1, a2, a3, bb[n][0], bb[n][1]);
            }
        }
        __syncthreads();   // all warps done reading K; KPs becomes P

        // ---- online softmax; P -> KPs (warp-local rows) --------------------
        #pragma unroll
        for (int hh = 0; hh < 2; hh++) {
            #pragma unroll
            for (int sl = 0; sl < 2; sl++) {
                const int si = hh * 2 + sl;
                const int c0 = sl * 2, c1 = sl * 2 + 1;
                float rmax = -1e30f;
                #pragma unroll
                for (int n = 0; n < 8; n++)
                    rmax = fmaxf(rmax, fmaxf(s[hh][n][c0], s[hh][n][c1]));
                rmax = fmaxf(rmax, __shfl_xor_sync(0xffffffffu, rmax, 1, 4));
                rmax = fmaxf(rmax, __shfl_xor_sync(0xffffffffu, rmax, 2, 4));
                float mnew = fmaxf(mrow[si], rmax);
                float corr = __expf(mrow[si] - mnew);
                float psum = 0.0f;
                const int prow = (m0 + hh * 16 + sl * 8 + g) * LS;
                #pragma unroll
                for (int n = 0; n < 8; n++) {
                    float p0 = __expf(s[hh][n][c0] - mnew);
                    float p1 = __expf(s[hh][n][c1] - mnew);
                    psum += p0 + p1;
                    *reinterpret_cast<float2*>(KPs + prow + n * 8 + 2 * t) =
                        make_float2(tf(p0), tf(p1));
                }
                psum += __shfl_xor_sync(0xffffffffu, psum, 1, 4);
                psum += __shfl_xor_sync(0xffffffffu, psum, 2, 4);
                lrow[si] = lrow[si] * corr + psum;
                mrow[si] = mnew;
                #pragma unroll
                for (int n = 0; n < 8; n++) { o[hh][n][c0] *= corr; o[hh][n][c1] *= corr; }
            }
        }
        // no barrier: each warp's P A-frags come from rows it wrote itself

        // ---- O += P V ------------------------------------------------------
        #pragma unroll
        for (int ks = 0; ks < 8; ks++) {
            uint32_t bb[8][2];
            #pragma unroll
            for (int np = 0; np < 4; np++)
                ldsm4(bb[2 * np][0], bb[2 * np][1], bb[2 * np + 1][0], bb[2 * np + 1][1],
                      bVbase + np * (16 * LS * 4) + ks * 32);
            #pragma unroll
            for (int hh = 0; hh < 2; hh++) {
                uint32_t a0, a1, a2, a3;
                ldsm4(a0, a1, a2, a3, aPbase + hh * (16 * LS * 4) + ks * 32);
                #pragma unroll
                for (int n = 0; n < 8; n++)
                    mma_tf32(o[hh][n], a0, a1, a2, a3, bb[n][0], bb[n][1]);
            }
        }
    }

    // Epilogue
    float* ob = g_attn + ((size_t)(b * SEQ + qt * BM + m0)) * DMODEL + h * HDIM;
    #pragma unroll
    for (int hh = 0; hh < 2; hh++) {
        float inv0 = 1.0f / lrow[hh * 2 + 0];
        float inv1 = 1.0f / lrow[hh * 2 + 1];
        #pragma unroll
        for (int n = 0; n < 8; n++) {
            *reinterpret_cast<float2*>(ob + (size_t)(hh * 16 + g) * DMODEL + n * 8 + 2 * t) =
                make_float2(o[hh][n][0] * inv0, o[hh][n][1] * inv0);
            *reinterpret_cast<float2*>(ob + (size_t)(hh * 16 + 8 + g) * DMODEL + n * 8 + 2 * t) =
                make_float2(o[hh][n][2] * inv1, o[hh][n][3] * inv1);
        }
    }
}

// ---------------------------------------------------------------------------
// Kernel 2: projection out = X @ W^T. Tile 128(M) x 64(N), 4 warps m32 each.
// ---------------------------------------------------------------------------
#define LX 36
#define LW 36

__global__ void __launch_bounds__(128)
proj_kernel(const float* __restrict__ W, float* __restrict__ out)
{
    __shared__ float Xs[128 * LX];
    __shared__ float Ws[64 * LW];

    const int tid  = threadIdx.x;
    const int lane = tid & 31;
    const int w    = tid >> 5;
    const int g    = lane >> 2;
    const int t    = lane & 3;
    const int m0   = w * 32;
    const int mi   = lane >> 3;
    const int rs   = lane & 7;
    const int rowBase = blockIdx.y * 128;
    const int colBase = blockIdx.x * 64;

    const uint32_t aXbase = smaddr(Xs + (m0 + rs + ((mi & 1) << 3)) * LX + ((mi >> 1) << 2));
    const uint32_t bWbase = smaddr(Ws + (rs + ((mi >> 1) << 3)) * LW + ((mi & 1) << 2));

    float acc[2][8][4];
    #pragma unroll
    for (int hh = 0; hh < 2; hh++)
        #pragma unroll
        for (int n = 0; n < 8; n++)
            #pragma unroll
            for (int j = 0; j < 4; j++) acc[hh][n][j] = 0.0f;

    for (int kt = 0; kt < DMODEL / 32; kt++) {
        #pragma unroll
        for (int i = tid; i < 128 * 8; i += 128) {
            int r = i >> 3, c = i & 7;
            float4 x = *reinterpret_cast<const float4*>(
                g_attn + (size_t)(rowBase + r) * DMODEL + kt * 32 + c * 4);
            float4 y;
            y.x = tf(x.x); y.y = tf(x.y); y.z = tf(x.z); y.w = tf(x.w);
            *reinterpret_cast<float4*>(Xs + r * LX + c * 4) = y;
        }
        #pragma unroll
        for (int i = tid; i < 64 * 8; i += 128) {
            int r = i >> 3, c = i & 7;
            float4 x = *reinterpret_cast<const float4*>(
                W + (size_t)(colBase + r) * DMODEL + kt * 32 + c * 4);
            float4 y;
            y.x = tf(x.x); y.y = tf(x.y); y.z = tf(x.z); y.w = tf(x.w);
            *reinterpret_cast<float4*>(Ws + r * LW + c * 4) = y;
        }
        __syncthreads();

        #pragma unroll
        for (int ks = 0; ks < 4; ks++) {
            uint32_t bb[8][2];
            #pragma unroll
            for (int np = 0; np < 4; np++)
                ldsm4(bb[2 * np][0], bb[2 * np][1], bb[2 * np + 1][0], bb[2 * np + 1][1],
                      bWbase + np * (16 * LW * 4) + ks * 32);
            #pragma unroll
            for (int hh = 0; hh < 2; hh++) {
                uint32_t a0, a1, a2, a3;
                ldsm4(a0, a1, a2, a3, aXbase + hh * (16 * LX * 4) + ks * 32);
                #pragma unroll
                for (int n = 0; n < 8; n++)
                    mma_tf32(acc[hh][n], a0, a1, a2, a3, bb[n][0], bb[n][1]);
            }
        }
        __syncthreads();
    }

    float* ob = out + (size_t)(rowBase + m0) * DMODEL + colBase;
    #pragma unroll
    for (int hh = 0; hh < 2; hh++)
        #pragma unroll
        for (int n = 0; n < 8; n++) {
            *reinterpret_cast<float2*>(ob + (size_t)(hh * 16 + g) * DMODEL + n * 8 + 2 * t) =
                make_float2(acc[hh][n][0], acc[hh][n][1]);
            *reinterpret_cast<float2*>(ob + (size_t)(hh * 16 + 8 + g) * DMODEL + n * 8 + 2 * t) =
                make_float2(acc[hh][n][2], acc[hh][n][3]);
        }
}

// ---------------------------------------------------------------------------
// Kernel 3: in-place row LayerNorm, row = 1024 floats.
// ---------------------------------------------------------------------------
__global__ void __launch_bounds__(256)
ln_kernel(float* __restrict__ out, const float* __restrict__ g)
{
    const int row = blockIdx.x;
    float* p = out + (size_t)row * DMODEL;
    const int tid = threadIdx.x;

    float4 x = reinterpret_cast<float4*>(p)[tid];
    float s  = x.x + x.y + x.z + x.w;
    float ss = x.x * x.x + x.y * x.y + x.z * x.z + x.w * x.w;

    #pragma unroll
    for (int off = 16; off > 0; off >>= 1) {
        s  += __shfl_xor_sync(0xffffffffu, s,  off);
        ss += __shfl_xor_sync(0xffffffffu, ss, off);
    }
    __shared__ float sbuf[8], ssbuf[8];
    if ((tid & 31) == 0) { sbuf[tid >> 5] = s; ssbuf[tid >> 5] = ss; }
    __syncthreads();
    s = 0.0f; ss = 0.0f;
    #pragma unroll
    for (int i = 0; i < 8; i++) { s += sbuf[i]; ss += ssbuf[i]; }

    const float mean = s * (1.0f / DMODEL);
    const float var  = ss * (1.0f / DMODEL) - mean * mean;
    const float rstd = rsqrtf(var + LN_EPS);

    float4 gv = reinterpret_cast<const float4*>(g)[tid];
    x.x = (x.x - mean) * rstd * gv.x;
    x.y = (x.y - mean) * rstd * gv.y;
    x.z = (x.z - mean) * rstd * gv.z;
    x.w = (x.w - mean) * rstd * gv.w;
    reinterpret_cast<float4*>(p)[tid] = x;
}

// ---------------------------------------------------------------------------
extern "C" void kernel_launch(void* const* d_in, const int* in_sizes, int n_in,
                              void* d_out, int out_size)
{
    const float* q  = (const float*)d_in[0];
    const float* k  = (const float*)d_in[1];
    const float* v  = (const float*)d_in[2];
    const float* W  = (const float*)d_in[3];
    const float* g  = (const float*)d_in[4];
    float* out = (float*)d_out;

    cudaFuncSetAttribute(attn_kernel,
                         cudaFuncAttributeMaxDynamicSharedMemorySize, ATT_SMEM_BYTES);

    dim3 vgrid(SEQ / 32, DMODEL / 32, BATCH);
    vt_kernel<<<vgrid, 256>>>(v);

    dim3 agrid(SEQ / BM, BATCH * HEADS);
    attn_kernel<<<agrid, 128, ATT_SMEM_BYTES>>>(q, k);

    dim3 pgrid(DMODEL / 64, BATCH * SEQ / 128);
    proj_kernel<<<pgrid, 128>>>(W, out);

    ln_kernel<<<BATCH * SEQ, 256>>>(out, g);
}

// round 6
// speedup vs baseline: 2.3155x; 1.5466x over previous
#include <cuda_runtime.h>
#include <cuda_fp16.h>
#include <cstdint>

// Problem constants
#define BATCH 4
#define HEADS 16
#define SEQ   2048
#define HDIM  64
#define DMODEL 1024
#define LN_EPS 1e-5f
#define LOG2E 1.4426950408889634f

// Attention tiling: BM=128 (4 warps, m32 each), BN=64 keys/tile.
#define BM 128
#define BN 64
#define NTILES (SEQ / BN)

// Smem stride in halves: 72 -> 144B rows (16B aligned), row advance = 4 banks:
// every ldmatrix 8-address phase (A, B, trans-B) is bank-conflict-free.
#define LH 72

// Scratch: attention output, stored as half (proj converts to half anyway)
__device__ __half g_attn[(size_t)BATCH * SEQ * DMODEL];

// ---- helpers --------------------------------------------------------------
__device__ __forceinline__ float ex2(float x) {
    float y;
    asm("ex2.approx.f32 %0, %1;" : "=f"(y) : "f"(x));
    return y;
}
__device__ __forceinline__ uint32_t smaddr(const void* p) {
    return (uint32_t)__cvta_generic_to_shared(p);
}
__device__ __forceinline__ void ldsm4(uint32_t& r0, uint32_t& r1,
                                      uint32_t& r2, uint32_t& r3, uint32_t a) {
    asm volatile("ldmatrix.sync.aligned.m8n8.x4.shared.b16 {%0,%1,%2,%3}, [%4];"
                 : "=r"(r0), "=r"(r1), "=r"(r2), "=r"(r3) : "r"(a));
}
__device__ __forceinline__ void ldsm4t(uint32_t& r0, uint32_t& r1,
                                       uint32_t& r2, uint32_t& r3, uint32_t a) {
    asm volatile("ldmatrix.sync.aligned.m8n8.x4.trans.shared.b16 {%0,%1,%2,%3}, [%4];"
                 : "=r"(r0), "=r"(r1), "=r"(r2), "=r"(r3) : "r"(a));
}
__device__ __forceinline__ void mma_f16(float c[4],
                                        uint32_t a0, uint32_t a1, uint32_t a2, uint32_t a3,
                                        uint32_t b0, uint32_t b1) {
    asm volatile(
        "mma.sync.aligned.m16n8k16.row.col.f32.f16.f16.f32 "
        "{%0,%1,%2,%3}, {%4,%5,%6,%7}, {%8,%9}, {%0,%1,%2,%3};\n"
        : "+f"(c[0]), "+f"(c[1]), "+f"(c[2]), "+f"(c[3])
        : "r"(a0), "r"(a1), "r"(a2), "r"(a3), "r"(b0), "r"(b1));
}
// pack 4 floats -> 4 halves as uint2 (one 8B STS)
__device__ __forceinline__ uint2 pack4h(float a, float b, float c, float d) {
    __half2 lo = __floats2half2_rn(a, b);
    __half2 hi = __floats2half2_rn(c, d);
    return make_uint2(*reinterpret_cast<uint32_t*>(&lo),
                      *reinterpret_cast<uint32_t*>(&hi));
}

// ---------------------------------------------------------------------------
// Kernel 1: flash attention, fp16 tensor cores (fp32 accum), log2-domain exp.
// grid (SEQ/BM=16, B*H=64), block 128 (4 warps, m32 each).
// ---------------------------------------------------------------------------
__global__ void __launch_bounds__(128)
attn_kernel(const float* __restrict__ q,
            const float* __restrict__ k,
            const float* __restrict__ v)
{
    __shared__ __half Qs [BM * LH];          // [128][72]
    __shared__ __half KPs[BM * LH];          // K rows 0..63, then P rows 0..127
    __shared__ __half Vs [BN * LH];          // [64][72] row-major [key][dim]

    const int bh = blockIdx.y;
    const int b  = bh >> 4;
    const int h  = bh & 15;
    const int qt = blockIdx.x;
    const int tid  = threadIdx.x;
    const int lane = tid & 31;
    const int w    = tid >> 5;
    const int g    = lane >> 2;
    const int t    = lane & 3;
    const int m0   = w * 32;

    const int mi = lane >> 3;     // ldmatrix group 0..3
    const int rs = lane & 7;      // row within group

    // A-pattern (Q/P): groups (rows m0+rs | m0+8+rs) x (colseg 0 | 1)
    const uint32_t aQbase = smaddr(Qs  + (m0 + rs + ((mi & 1) << 3)) * LH + ((mi >> 1) << 3));
    const uint32_t aPbase = smaddr(KPs + (m0 + rs + ((mi & 1) << 3)) * LH + ((mi >> 1) << 3));
    // B-pattern (K): groups (rows rs | 8+rs along n) x (kseg 0 | 1)
    const uint32_t bKbase = smaddr(KPs + (rs + ((mi >> 1) << 3)) * LH + ((mi & 1) << 3));
    // B-pattern (V, trans): groups (rows rs | 8+rs along k=j) x (dseg 0 | 1)
    const uint32_t bVbase = smaddr(Vs  + (rs + ((mi & 1) << 3)) * LH + ((mi >> 1) << 3));

    const float qscale = 0.125f * LOG2E;     // fold softmax scale + log2e

    // Q fill: coalesced float4 loads, cvt to half, 8B stores
    const float* qb = q + ((size_t)(b * SEQ + qt * BM)) * DMODEL + h * HDIM;
    #pragma unroll
    for (int i = tid; i < BM * 16; i += 128) {
        int r = i >> 4, c = i & 15;
        float4 x = *reinterpret_cast<const float4*>(qb + (size_t)r * DMODEL + c * 4);
        *reinterpret_cast<uint2*>(Qs + r * LH + c * 4) =
            pack4h(x.x * qscale, x.y * qscale, x.z * qscale, x.w * qscale);
    }

    float o[2][8][4];
    #pragma unroll
    for (int hh = 0; hh < 2; hh++)
        #pragma unroll
        for (int n = 0; n < 8; n++)
            #pragma unroll
            for (int j = 0; j < 4; j++) o[hh][n][j] = 0.0f;
    float mrow[4] = {-1e30f, -1e30f, -1e30f, -1e30f};
    float lrow[4] = {0.0f, 0.0f, 0.0f, 0.0f};

    const float* kb0 = k + ((size_t)b * SEQ) * DMODEL + h * HDIM;
    const float* vb0 = v + ((size_t)b * SEQ) * DMODEL + h * HDIM;

    for (int ti = 0; ti < NTILES; ti++) {
        __syncthreads();   // prior tile fully consumed
        const float* kb = kb0 + (size_t)(ti * BN) * DMODEL;
        const float* vb = vb0 + (size_t)(ti * BN) * DMODEL;
        #pragma unroll
        for (int i = tid; i < BN * 16; i += 128) {
            int r = i >> 4, c = i & 15;
            float4 xk = *reinterpret_cast<const float4*>(kb + (size_t)r * DMODEL + c * 4);
            float4 xv = *reinterpret_cast<const float4*>(vb + (size_t)r * DMODEL + c * 4);
            *reinterpret_cast<uint2*>(KPs + r * LH + c * 4) = pack4h(xk.x, xk.y, xk.z, xk.w);
            *reinterpret_cast<uint2*>(Vs  + r * LH + c * 4) = pack4h(xv.x, xv.y, xv.z, xv.w);
        }
        __syncthreads();

        // ---- S = Q K^T (4 k16 chunks) --------------------------------------
        float s[2][8][4];
        #pragma unroll
        for (int hh = 0; hh < 2; hh++)
            #pragma unroll
            for (int n = 0; n < 8; n++)
                #pragma unroll
                for (int j = 0; j < 4; j++) s[hh][n][j] = 0.0f;

        #pragma unroll
        for (int ks = 0; ks < 4; ks++) {
            uint32_t av[2][4];
            #pragma unroll
            for (int hh = 0; hh < 2; hh++)
                ldsm4(av[hh][0], av[hh][1], av[hh][2], av[hh][3],
                      aQbase + hh * (16 * LH * 2) + ks * 32);
            uint32_t bb[8][2];
            #pragma unroll
            for (int np = 0; np < 4; np++)
                ldsm4(bb[2 * np][0], bb[2 * np][1], bb[2 * np + 1][0], bb[2 * np + 1][1],
                      bKbase + np * (16 * LH * 2) + ks * 32);
            #pragma unroll
            for (int hh = 0; hh < 2; hh++)
                #pragma unroll
                for (int n = 0; n < 8; n++)
                    mma_f16(s[hh][n], av[hh][0], av[hh][1], av[hh][2], av[hh][3],
                            bb[n][0], bb[n][1]);
        }
        __syncthreads();   // all warps done reading K; KPs becomes P

        // ---- online softmax (log2 domain); P (half) -> KPs -----------------
        #pragma unroll
        for (int hh = 0; hh < 2; hh++) {
            #pragma unroll
            for (int sl = 0; sl < 2; sl++) {
                const int si = hh * 2 + sl;
                const int c0 = sl * 2, c1 = sl * 2 + 1;
                float rmax = -1e30f;
                #pragma unroll
                for (int n = 0; n < 8; n++)
                    rmax = fmaxf(rmax, fmaxf(s[hh][n][c0], s[hh][n][c1]));
                rmax = fmaxf(rmax, __shfl_xor_sync(0xffffffffu, rmax, 1, 4));
                rmax = fmaxf(rmax, __shfl_xor_sync(0xffffffffu, rmax, 2, 4));
                float mnew = fmaxf(mrow[si], rmax);
                float corr = ex2(mrow[si] - mnew);
                float psum = 0.0f;
                const int prow = (m0 + hh * 16 + sl * 8 + g) * LH;
                #pragma unroll
                for (int n = 0; n < 8; n++) {
                    float p0 = ex2(s[hh][n][c0] - mnew);
                    float p1 = ex2(s[hh][n][c1] - mnew);
                    psum += p0 + p1;
                    *reinterpret_cast<__half2*>(KPs + prow + n * 8 + 2 * t) =
                        __floats2half2_rn(p0, p1);
                }
                psum += __shfl_xor_sync(0xffffffffu, psum, 1, 4);
                psum += __shfl_xor_sync(0xffffffffu, psum, 2, 4);
                lrow[si] = lrow[si] * corr + psum;
                mrow[si] = mnew;
                #pragma unroll
                for (int n = 0; n < 8; n++) { o[hh][n][c0] *= corr; o[hh][n][c1] *= corr; }
            }
        }
        // no barrier: warp's P A-frags come from rows it wrote itself

        // ---- O += P V (B-frags via ldmatrix.trans from row-major V) --------
        #pragma unroll
        for (int ks = 0; ks < 4; ks++) {
            uint32_t av[2][4];
            #pragma unroll
            for (int hh = 0; hh < 2; hh++)
                ldsm4(av[hh][0], av[hh][1], av[hh][2], av[hh][3],
                      aPbase + hh * (16 * LH * 2) + ks * 32);
            uint32_t bb[8][2];
            #pragma unroll
            for (int dp = 0; dp < 4; dp++)
                ldsm4t(bb[2 * dp][0], bb[2 * dp][1], bb[2 * dp + 1][0], bb[2 * dp + 1][1],
                       bVbase + ks * (16 * LH * 2) + dp * 32);
            #pragma unroll
            for (int hh = 0; hh < 2; hh++)
                #pragma unroll
                for (int n = 0; n < 8; n++)
                    mma_f16(o[hh][n], av[hh][0], av[hh][1], av[hh][2], av[hh][3],
                            bb[n][0], bb[n][1]);
        }
    }

    // Epilogue: normalize, store half
    __half* ob = g_attn + ((size_t)(b * SEQ + qt * BM + m0)) * DMODEL + h * HDIM;
    #pragma unroll
    for (int hh = 0; hh < 2; hh++) {
        float inv0 = 1.0f / lrow[hh * 2 + 0];
        float inv1 = 1.0f / lrow[hh * 2 + 1];
        #pragma unroll
        for (int n = 0; n < 8; n++) {
            *reinterpret_cast<__half2*>(ob + (size_t)(hh * 16 + g) * DMODEL + n * 8 + 2 * t) =
                __floats2half2_rn(o[hh][n][0] * inv0, o[hh][n][1] * inv0);
            *reinterpret_cast<__half2*>(ob + (size_t)(hh * 16 + 8 + g) * DMODEL + n * 8 + 2 * t) =
                __floats2half2_rn(o[hh][n][2] * inv1, o[hh][n][3] * inv1);
        }
    }
}

// ---------------------------------------------------------------------------
// Kernel 2: projection out = X @ W^T, fp16 mma (fp32 accum).
// Tile 128(M) x 64(N), Kchunk 64. Block 128 (4 warps, m32 each).
// ---------------------------------------------------------------------------
__global__ void __launch_bounds__(128)
proj_kernel(const float* __restrict__ W, float* __restrict__ out)
{
    __shared__ __half Xs[128 * LH];
    __shared__ __half Ws[64 * LH];

    const int tid  = threadIdx.x;
    const int lane = tid & 31;
    const int w    = tid >> 5;
    const int g    = lane >> 2;
    const int t    = lane & 3;
    const int m0   = w * 32;
    const int mi   = lane >> 3;
    const int rs   = lane & 7;
    const int rowBase = blockIdx.y * 128;
    const int colBase = blockIdx.x * 64;

    const uint32_t aXbase = smaddr(Xs + (m0 + rs + ((mi & 1) << 3)) * LH + ((mi >> 1) << 3));
    const uint32_t bWbase = smaddr(Ws + (rs + ((mi >> 1) << 3)) * LH + ((mi & 1) << 3));

    float acc[2][8][4];
    #pragma unroll
    for (int hh = 0; hh < 2; hh++)
        #pragma unroll
        for (int n = 0; n < 8; n++)
            #pragma unroll
            for (int j = 0; j < 4; j++) acc[hh][n][j] = 0.0f;

    for (int kt = 0; kt < DMODEL / 64; kt++) {
        // X: already half in g_attn -> straight 8B copies
        #pragma unroll
        for (int i = tid; i < 128 * 16; i += 128) {
            int r = i >> 4, c = i & 15;
            uint2 x = *reinterpret_cast<const uint2*>(
                g_attn + (size_t)(rowBase + r) * DMODEL + kt * 64 + c * 4);
            *reinterpret_cast<uint2*>(Xs + r * LH + c * 4) = x;
        }
        // W: fp32 -> half
        #pragma unroll
        for (int i = tid; i < 64 * 16; i += 128) {
            int r = i >> 4, c = i & 15;
            float4 x = *reinterpret_cast<const float4*>(
                W + (size_t)(colBase + r) * DMODEL + kt * 64 + c * 4);
            *reinterpret_cast<uint2*>(Ws + r * LH + c * 4) = pack4h(x.x, x.y, x.z, x.w);
        }
        __syncthreads();

        #pragma unroll
        for (int ks = 0; ks < 4; ks++) {
            uint32_t av[2][4];
            #pragma unroll
            for (int hh = 0; hh < 2; hh++)
                ldsm4(av[hh][0], av[hh][1], av[hh][2], av[hh][3],
                      aXbase + hh * (16 * LH * 2) + ks * 32);
            uint32_t bb[8][2];
            #pragma unroll
            for (int np = 0; np < 4; np++)
                ldsm4(bb[2 * np][0], bb[2 * np][1], bb[2 * np + 1][0], bb[2 * np + 1][1],
                      bWbase + np * (16 * LH * 2) + ks * 32);
            #pragma unroll
            for (int hh = 0; hh < 2; hh++)
                #pragma unroll
                for (int n = 0; n < 8; n++)
                    mma_f16(acc[hh][n], av[hh][0], av[hh][1], av[hh][2], av[hh][3],
                            bb[n][0], bb[n][1]);
        }
        __syncthreads();
    }

    float* ob = out + (size_t)(rowBase + m0) * DMODEL + colBase;
    #pragma unroll
    for (int hh = 0; hh < 2; hh++)
        #pragma unroll
        for (int n = 0; n < 8; n++) {
            *reinterpret_cast<float2*>(ob + (size_t)(hh * 16 + g) * DMODEL + n * 8 + 2 * t) =
                make_float2(acc[hh][n][0], acc[hh][n][1]);
            *reinterpret_cast<float2*>(ob + (size_t)(hh * 16 + 8 + g) * DMODEL + n * 8 + 2 * t) =
                make_float2(acc[hh][n][2], acc[hh][n][3]);
        }
}

// ---------------------------------------------------------------------------
// Kernel 3: in-place row LayerNorm, row = 1024 floats.
// ---------------------------------------------------------------------------
__global__ void __launch_bounds__(256)
ln_kernel(float* __restrict__ out, const float* __restrict__ g)
{
    const int row = blockIdx.x;
    float* p = out + (size_t)row * DMODEL;
    const int tid = threadIdx.x;

    float4 x = reinterpret_cast<float4*>(p)[tid];
    float s  = x.x + x.y + x.z + x.w;
    float ss = x.x * x.x + x.y * x.y + x.z * x.z + x.w * x.w;

    #pragma unroll
    for (int off = 16; off > 0; off >>= 1) {
        s  += __shfl_xor_sync(0xffffffffu, s,  off);
        ss += __shfl_xor_sync(0xffffffffu, ss, off);
    }
    __shared__ float sbuf[8], ssbuf[8];
    if ((tid & 31) == 0) { sbuf[tid >> 5] = s; ssbuf[tid >> 5] = ss; }
    __syncthreads();
    s = 0.0f; ss = 0.0f;
    #pragma unroll
    for (int i = 0; i < 8; i++) { s += sbuf[i]; ss += ssbuf[i]; }

    const float mean = s * (1.0f / DMODEL);
    const float var  = ss * (1.0f / DMODEL) - mean * mean;
    const float rstd = rsqrtf(var + LN_EPS);

    float4 gv = reinterpret_cast<const float4*>(g)[tid];
    x.x = (x.x - mean) * rstd * gv.x;
    x.y = (x.y - mean) * rstd * gv.y;
    x.z = (x.z - mean) * rstd * gv.z;
    x.w = (x.w - mean) * rstd * gv.w;
    reinterpret_cast<float4*>(p)[tid] = x;
}

// ---------------------------------------------------------------------------
extern "C" void kernel_launch(void* const* d_in, const int* in_sizes, int n_in,
                              void* d_out, int out_size)
{
    const float* q  = (const float*)d_in[0];
    const float* k  = (const float*)d_in[1];
    const float* v  = (const float*)d_in[2];
    const float* W  = (const float*)d_in[3];
    const float* g  = (const float*)d_in[4];
    float* out = (float*)d_out;

    dim3 agrid(SEQ / BM, BATCH * HEADS);
    attn_kernel<<<agrid, 128>>>(q, k, v);

    dim3 pgrid(DMODEL / 64, BATCH * SEQ / 128);
    proj_kernel<<<pgrid, 128>>>(W, out);

    ln_kernel<<<BATCH * SEQ, 256>>>(out, g);
}

// round 7
// speedup vs baseline: 3.1871x; 1.3764x over previous
#include <cuda_runtime.h>
#include <cuda_fp16.h>
#include <cstdint>

// Problem constants
#define BATCH 4
#define HEADS 16
#define SEQ   2048
#define HDIM  64
#define DMODEL 1024
#define LN_EPS 1e-5f
#define LOG2E 1.4426950408889634f

// Attention tiling: BM=128 (4 warps, m32 each), BN=64 keys/tile, 2-stage pipe.
#define BM 128
#define BN 64
#define NTILES (SEQ / BN)

// Smem stride in halves: 72 -> 144B rows (16B aligned), row advance = 4 banks:
// every ldmatrix 8-address phase (A, B, trans-B) is bank-conflict-free.
#define LH 72
#define KSTB (BN * LH * 2)                 // K/V stage bytes = 9216
#define ATT_SMEM_BYTES ((BM + BM + 2*BN + 2*BN) * LH * 2)   // 73728

// Pre-converted half operands (16B aligned for cp.async)
__device__ __align__(16) __half g_qh[(size_t)BATCH * SEQ * DMODEL];   // q*scale*log2e
__device__ __align__(16) __half g_kh[(size_t)BATCH * SEQ * DMODEL];
__device__ __align__(16) __half g_vh[(size_t)BATCH * SEQ * DMODEL];
__device__ __align__(16) __half g_wh[(size_t)DMODEL * DMODEL];
__device__ __align__(16) __half g_attn[(size_t)BATCH * SEQ * DMODEL];

// ---- helpers --------------------------------------------------------------
__device__ __forceinline__ float ex2(float x) {
    float y;
    asm("ex2.approx.f32 %0, %1;" : "=f"(y) : "f"(x));
    return y;
}
__device__ __forceinline__ __half2 h2ex2(__half2 x) {
    uint32_t xi = *reinterpret_cast<uint32_t*>(&x), yi;
    asm("ex2.approx.f16x2 %0, %1;" : "=r"(yi) : "r"(xi));
    return *reinterpret_cast<__half2*>(&yi);
}
__device__ __forceinline__ uint32_t smaddr(const void* p) {
    return (uint32_t)__cvta_generic_to_shared(p);
}
__device__ __forceinline__ void cpa16(uint32_t s, const void* g) {
    asm volatile("cp.async.cg.shared.global [%0], [%1], 16;"
                 :: "r"(s), "l"(__cvta_generic_to_global(g)) : "memory");
}
#define CP_COMMIT() asm volatile("cp.async.commit_group;" ::: "memory")
#define CP_WAIT0()  asm volatile("cp.async.wait_group 0;" ::: "memory")

__device__ __forceinline__ void ldsm4(uint32_t& r0, uint32_t& r1,
                                      uint32_t& r2, uint32_t& r3, uint32_t a) {
    asm volatile("ldmatrix.sync.aligned.m8n8.x4.shared.b16 {%0,%1,%2,%3}, [%4];"
                 : "=r"(r0), "=r"(r1), "=r"(r2), "=r"(r3) : "r"(a));
}
__device__ __forceinline__ void ldsm4t(uint32_t& r0, uint32_t& r1,
                                       uint32_t& r2, uint32_t& r3, uint32_t a) {
    asm volatile("ldmatrix.sync.aligned.m8n8.x4.trans.shared.b16 {%0,%1,%2,%3}, [%4];"
                 : "=r"(r0), "=r"(r1), "=r"(r2), "=r"(r3) : "r"(a));
}
__device__ __forceinline__ void mma_f16(float c[4],
                                        uint32_t a0, uint32_t a1, uint32_t a2, uint32_t a3,
                                        uint32_t b0, uint32_t b1) {
    asm volatile(
        "mma.sync.aligned.m16n8k16.row.col.f32.f16.f16.f32 "
        "{%0,%1,%2,%3}, {%4,%5,%6,%7}, {%8,%9}, {%0,%1,%2,%3};\n"
        : "+f"(c[0]), "+f"(c[1]), "+f"(c[2]), "+f"(c[3])
        : "r"(a0), "r"(a1), "r"(a2), "r"(a3), "r"(b0), "r"(b1));
}
__device__ __forceinline__ uint2 pack4h(float a, float b, float c, float d) {
    __half2 lo = __floats2half2_rn(a, b);
    __half2 hi = __floats2half2_rn(c, d);
    return make_uint2(*reinterpret_cast<uint32_t*>(&lo),
                      *reinterpret_cast<uint32_t*>(&hi));
}

// ---------------------------------------------------------------------------
// Kernel 0a: q/k/v -> half (q pre-scaled into log2 domain)
// ---------------------------------------------------------------------------
__global__ void __launch_bounds__(256)
prep_qkv(const float* __restrict__ q, const float* __restrict__ k,
         const float* __restrict__ v)
{
    size_t i = (size_t)blockIdx.x * 256 + threadIdx.x;   // float4 index
    const float s = 0.125f * LOG2E;
    float4 xq = reinterpret_cast<const float4*>(q)[i];
    float4 xk = reinterpret_cast<const float4*>(k)[i];
    float4 xv = reinterpret_cast<const float4*>(v)[i];
    reinterpret_cast<uint2*>(g_qh)[i] = pack4h(xq.x * s, xq.y * s, xq.z * s, xq.w * s);
    reinterpret_cast<uint2*>(g_kh)[i] = pack4h(xk.x, xk.y, xk.z, xk.w);
    reinterpret_cast<uint2*>(g_vh)[i] = pack4h(xv.x, xv.y, xv.z, xv.w);
}

// ---------------------------------------------------------------------------
// Kernel 0b: W -> half
// ---------------------------------------------------------------------------
__global__ void __launch_bounds__(256)
prep_w(const float* __restrict__ W)
{
    size_t i = (size_t)blockIdx.x * 256 + threadIdx.x;
    float4 x = reinterpret_cast<const float4*>(W)[i];
    reinterpret_cast<uint2*>(g_wh)[i] = pack4h(x.x, x.y, x.z, x.w);
}

// ---------------------------------------------------------------------------
// Kernel 1: flash attention, fp16 mma + cp.async 2-stage pipeline.
// grid (SEQ/BM=16, B*H=64), block 128 (4 warps, m32 each). 1 sync per tile.
// ---------------------------------------------------------------------------
__global__ void __launch_bounds__(128)
attn_kernel()
{
    extern __shared__ __half smh[];
    __half* Qs = smh;                        // [128][72]
    __half* Ps = Qs + BM * LH;               // [128][72]
    __half* Kb = Ps + BM * LH;               // 2 x [64][72]
    __half* Vb = Kb + 2 * BN * LH;           // 2 x [64][72]

    const int bh = blockIdx.y;
    const int b  = bh >> 4;
    const int h  = bh & 15;
    const int qt = blockIdx.x;
    const int tid  = threadIdx.x;
    const int lane = tid & 31;
    const int w    = tid >> 5;
    const int g    = lane >> 2;
    const int t    = lane & 3;
    const int m0   = w * 32;

    const int mi = lane >> 3;
    const int rs = lane & 7;

    const uint32_t aQbase = smaddr(Qs + (m0 + rs + ((mi & 1) << 3)) * LH + ((mi >> 1) << 3));
    const uint32_t aPbase = smaddr(Ps + (m0 + rs + ((mi & 1) << 3)) * LH + ((mi >> 1) << 3));
    const uint32_t bKbase = smaddr(Kb + (rs + ((mi >> 1) << 3)) * LH + ((mi & 1) << 3));
    const uint32_t bVbase = smaddr(Vb + (rs + ((mi & 1) << 3)) * LH + ((mi >> 1) << 3));
    const uint32_t kFill  = smaddr(Kb);
    const uint32_t vFill  = smaddr(Vb);

    const __half* qsrc  = g_qh + ((size_t)(b * SEQ + qt * BM)) * DMODEL + h * HDIM;
    const __half* ksrc0 = g_kh + ((size_t)b * SEQ) * DMODEL + h * HDIM;
    const __half* vsrc0 = g_vh + ((size_t)b * SEQ) * DMODEL + h * HDIM;

    // Prologue: Q + stage-0 K/V via cp.async (one commit group)
    #pragma unroll
    for (int i = tid; i < BM * 8; i += 128) {
        int r = i >> 3, c = i & 7;
        cpa16(smaddr(Qs + r * LH + c * 8), qsrc + (size_t)r * DMODEL + c * 8);
    }
    #pragma unroll
    for (int i = tid; i < BN * 8; i += 128) {
        int r = i >> 3, c = i & 7;
        cpa16(kFill + r * 144 + c * 16, ksrc0 + (size_t)r * DMODEL + c * 8);
        cpa16(vFill + r * 144 + c * 16, vsrc0 + (size_t)r * DMODEL + c * 8);
    }
    CP_COMMIT();

    float o[2][8][4];
    #pragma unroll
    for (int hh = 0; hh < 2; hh++)
        #pragma unroll
        for (int n = 0; n < 8; n++)
            #pragma unroll
            for (int j = 0; j < 4; j++) o[hh][n][j] = 0.0f;
    float mrow[4] = {-1e30f, -1e30f, -1e30f, -1e30f};
    float lrow[4] = {0.0f, 0.0f, 0.0f, 0.0f};

    for (int ti = 0; ti < NTILES; ti++) {
        const uint32_t cur = (uint32_t)(ti & 1) * KSTB;
        CP_WAIT0();
        __syncthreads();   // tile ti visible to all; all warps done with prior stage

        // Issue tile ti+1 into the other stage (overlaps with this compute)
        if (ti + 1 < NTILES) {
            const uint32_t nst = (uint32_t)((ti + 1) & 1) * KSTB;
            const __half* kn = ksrc0 + (size_t)((ti + 1) * BN) * DMODEL;
            const __half* vn = vsrc0 + (size_t)((ti + 1) * BN) * DMODEL;
            #pragma unroll
            for (int i = tid; i < BN * 8; i += 128) {
                int r = i >> 3, c = i & 7;
                cpa16(kFill + nst + r * 144 + c * 16, kn + (size_t)r * DMODEL + c * 8);
                cpa16(vFill + nst + r * 144 + c * 16, vn + (size_t)r * DMODEL + c * 8);
            }
        }
        CP_COMMIT();

        // ---- S = Q K^T -----------------------------------------------------
        float s[2][8][4];
        #pragma unroll
        for (int hh = 0; hh < 2; hh++)
            #pragma unroll
            for (int n = 0; n < 8; n++)
                #pragma unroll
                for (int j = 0; j < 4; j++) s[hh][n][j] = 0.0f;

        #pragma unroll
        for (int ks = 0; ks < 4; ks++) {
            uint32_t av[2][4];
            #pragma unroll
            for (int hh = 0; hh < 2; hh++)
                ldsm4(av[hh][0], av[hh][1], av[hh][2], av[hh][3],
                      aQbase + hh * (16 * LH * 2) + ks * 32);
            uint32_t bb[8][2];
            #pragma unroll
            for (int np = 0; np < 4; np++)
                ldsm4(bb[2 * np][0], bb[2 * np][1], bb[2 * np + 1][0], bb[2 * np + 1][1],
                      bKbase + cur + np * (16 * LH * 2) + ks * 32);
            #pragma unroll
            for (int hh = 0; hh < 2; hh++)
                #pragma unroll
                for (int n = 0; n < 8; n++)
                    mma_f16(s[hh][n], av[hh][0], av[hh][1], av[hh][2], av[hh][3],
                            bb[n][0], bb[n][1]);
        }

        // ---- online softmax (log2 domain, f16x2 exp); P -> Ps --------------
        #pragma unroll
        for (int hh = 0; hh < 2; hh++) {
            #pragma unroll
            for (int sl = 0; sl < 2; sl++) {
                const int si = hh * 2 + sl;
                const int c0 = sl * 2, c1 = sl * 2 + 1;
                float rmax = -1e30f;
                #pragma unroll
                for (int n = 0; n < 8; n++)
                    rmax = fmaxf(rmax, fmaxf(s[hh][n][c0], s[hh][n][c1]));
                rmax = fmaxf(rmax, __shfl_xor_sync(0xffffffffu, rmax, 1, 4));
                rmax = fmaxf(rmax, __shfl_xor_sync(0xffffffffu, rmax, 2, 4));
                float mnew = fmaxf(mrow[si], rmax);
                float corr = ex2(mrow[si] - mnew);
                float psum = 0.0f;
                const int prow = (m0 + hh * 16 + sl * 8 + g) * LH;
                #pragma unroll
                for (int n = 0; n < 8; n++) {
                    __half2 e = h2ex2(__floats2half2_rn(s[hh][n][c0] - mnew,
                                                        s[hh][n][c1] - mnew));
                    *reinterpret_cast<__half2*>(Ps + prow + n * 8 + 2 * t) = e;
                    float2 ef = __half22float2(e);
                    psum += ef.x + ef.y;
                }
                psum += __shfl_xor_sync(0xffffffffu, psum, 1, 4);
                psum += __shfl_xor_sync(0xffffffffu, psum, 2, 4);
                lrow[si] = lrow[si] * corr + psum;
                mrow[si] = mnew;
                #pragma unroll
                for (int n = 0; n < 8; n++) { o[hh][n][c0] *= corr; o[hh][n][c1] *= corr; }
            }
        }
        // no barrier: each warp's P A-frags come from its own rows

        // ---- O += P V ------------------------------------------------------
        #pragma unroll
        for (int ks = 0; ks < 4; ks++) {
            uint32_t av[2][4];
            #pragma unroll
            for (int hh = 0; hh < 2; hh++)
                ldsm4(av[hh][0], av[hh][1], av[hh][2], av[hh][3],
                      aPbase + hh * (16 * LH * 2) + ks * 32);
            uint32_t bb[8][2];
            #pragma unroll
            for (int dp = 0; dp < 4; dp++)
                ldsm4t(bb[2 * dp][0], bb[2 * dp][1], bb[2 * dp + 1][0], bb[2 * dp + 1][1],
                       bVbase + cur + ks * (16 * LH * 2) + dp * 32);
            #pragma unroll
            for (int hh = 0; hh < 2; hh++)
                #pragma unroll
                for (int n = 0; n < 8; n++)
                    mma_f16(o[hh][n], av[hh][0], av[hh][1], av[hh][2], av[hh][3],
                            bb[n][0], bb[n][1]);
        }
    }

    // Epilogue: normalize, store half
    __half* ob = g_attn + ((size_t)(b * SEQ + qt * BM + m0)) * DMODEL + h * HDIM;
    #pragma unroll
    for (int hh = 0; hh < 2; hh++) {
        float inv0 = 1.0f / lrow[hh * 2 + 0];
        float inv1 = 1.0f / lrow[hh * 2 + 1];
        #pragma unroll
        for (int n = 0; n < 8; n++) {
            *reinterpret_cast<__half2*>(ob + (size_t)(hh * 16 + g) * DMODEL + n * 8 + 2 * t) =
                __floats2half2_rn(o[hh][n][0] * inv0, o[hh][n][1] * inv0);
            *reinterpret_cast<__half2*>(ob + (size_t)(hh * 16 + 8 + g) * DMODEL + n * 8 + 2 * t) =
                __floats2half2_rn(o[hh][n][2] * inv1, o[hh][n][3] * inv1);
        }
    }
}

// ---------------------------------------------------------------------------
// Kernel 2: projection out = X @ W^T, fp16 mma + cp.async 2-stage pipeline.
// Tile 128(M) x 64(N), Kchunk 64, 16 chunks. Block 128 (4 warps, m32 each).
// ---------------------------------------------------------------------------
#define PXSTB (128 * LH * 2)     // X stage bytes = 18432
#define PWSTB (64 * LH * 2)      // W stage bytes = 9216
#define PROJ_SMEM_BYTES (2 * PXSTB + 2 * PWSTB)   // 55296
#define NKT (DMODEL / 64)

__global__ void __launch_bounds__(128)
proj_kernel(float* __restrict__ out)
{
    extern __shared__ __half smp[];
    __half* Xs = smp;                        // 2 x [128][72]
    __half* Ws = smp + 2 * 128 * LH;         // 2 x [64][72]

    const int tid  = threadIdx.x;
    const int lane = tid & 31;
    const int w    = tid >> 5;
    const int g    = lane >> 2;
    const int t    = lane & 3;
    const int m0   = w * 32;
    const int mi   = lane >> 3;
    const int rs   = lane & 7;
    const int rowBase = blockIdx.y * 128;
    const int colBase = blockIdx.x * 64;

    const uint32_t aXbase = smaddr(Xs + (m0 + rs + ((mi & 1) << 3)) * LH + ((mi >> 1) << 3));
    const uint32_t bWbase = smaddr(Ws + (rs + ((mi >> 1) << 3)) * LH + ((mi & 1) << 3));
    const uint32_t xFill  = smaddr(Xs);
    const uint32_t wFill  = smaddr(Ws);

    const __half* xsrc = g_attn + (size_t)rowBase * DMODEL;
    const __half* wsrc = g_wh + (size_t)colBase * DMODEL;

    // Prologue: stage 0
    #pragma unroll
    for (int i = tid; i < 128 * 8; i += 128) {
        int r = i >> 3, c = i & 7;
        cpa16(xFill + r * 144 + c * 16, xsrc + (size_t)r * DMODEL + c * 8);
    }
    #pragma unroll
    for (int i = tid; i < 64 * 8; i += 128) {
        int r = i >> 3, c = i & 7;
        cpa16(wFill + r * 144 + c * 16, wsrc + (size_t)r * DMODEL + c * 8);
    }
    CP_COMMIT();

    float acc[2][8][4];
    #pragma unroll
    for (int hh = 0; hh < 2; hh++)
        #pragma unroll
        for (int n = 0; n < 8; n++)
            #pragma unroll
            for (int j = 0; j < 4; j++) acc[hh][n][j] = 0.0f;

    for (int kt = 0; kt < NKT; kt++) {
        const uint32_t curX = (uint32_t)(kt & 1) * PXSTB;
        const uint32_t curW = (uint32_t)(kt & 1) * PWSTB;
        CP_WAIT0();
        __syncthreads();

        if (kt + 1 < NKT) {
            const uint32_t nX = (uint32_t)((kt + 1) & 1) * PXSTB;
            const uint32_t nW = (uint32_t)((kt + 1) & 1) * PWSTB;
            const __half* xn = xsrc + (kt + 1) * 64;
            const __half* wn = wsrc + (kt + 1) * 64;
            #pragma unroll
            for (int i = tid; i < 128 * 8; i += 128) {
                int r = i >> 3, c = i & 7;
                cpa16(xFill + nX + r * 144 + c * 16, xn + (size_t)r * DMODEL + c * 8);
            }
            #pragma unroll
            for (int i = tid; i < 64 * 8; i += 128) {
                int r = i >> 3, c = i & 7;
                cpa16(wFill + nW + r * 144 + c * 16, wn + (size_t)r * DMODEL + c * 8);
            }
        }
        CP_COMMIT();

        #pragma unroll
        for (int ks = 0; ks < 4; ks++) {
            uint32_t av[2][4];
            #pragma unroll
            for (int hh = 0; hh < 2; hh++)
                ldsm4(av[hh][0], av[hh][1], av[hh][2], av[hh][3],
                      aXbase + curX + hh * (16 * LH * 2) + ks * 32);
            uint32_t bb[8][2];
            #pragma unroll
            for (int np = 0; np < 4; np++)
                ldsm4(bb[2 * np][0], bb[2 * np][1], bb[2 * np + 1][0], bb[2 * np + 1][1],
                      bWbase + curW + np * (16 * LH * 2) + ks * 32);
            #pragma unroll
            for (int hh = 0; hh < 2; hh++)
                #pragma unroll
                for (int n = 0; n < 8; n++)
                    mma_f16(acc[hh][n], av[hh][0], av[hh][1], av[hh][2], av[hh][3],
                            bb[n][0], bb[n][1]);
        }
    }

    float* ob = out + (size_t)(rowBase + m0) * DMODEL + colBase;
    #pragma unroll
    for (int hh = 0; hh < 2; hh++)
        #pragma unroll
        for (int n = 0; n < 8; n++) {
            *reinterpret_cast<float2*>(ob + (size_t)(hh * 16 + g) * DMODEL + n * 8 + 2 * t) =
                make_float2(acc[hh][n][0], acc[hh][n][1]);
            *reinterpret_cast<float2*>(ob + (size_t)(hh * 16 + 8 + g) * DMODEL + n * 8 + 2 * t) =
                make_float2(acc[hh][n][2], acc[hh][n][3]);
        }
}

// ---------------------------------------------------------------------------
// Kernel 3: in-place row LayerNorm, row = 1024 floats.
// ---------------------------------------------------------------------------
__global__ void __launch_bounds__(256)
ln_kernel(float* __restrict__ out, const float* __restrict__ g)
{
    const int row = blockIdx.x;
    float* p = out + (size_t)row * DMODEL;
    const int tid = threadIdx.x;

    float4 x = reinterpret_cast<float4*>(p)[tid];
    float s  = x.x + x.y + x.z + x.w;
    float ss = x.x * x.x + x.y * x.y + x.z * x.z + x.w * x.w;

    #pragma unroll
    for (int off = 16; off > 0; off >>= 1) {
        s  += __shfl_xor_sync(0xffffffffu, s,  off);
        ss += __shfl_xor_sync(0xffffffffu, ss, off);
    }
    __shared__ float sbuf[8], ssbuf[8];
    if ((tid & 31) == 0) { sbuf[tid >> 5] = s; ssbuf[tid >> 5] = ss; }
    __syncthreads();
    s = 0.0f; ss = 0.0f;
    #pragma unroll
    for (int i = 0; i < 8; i++) { s += sbuf[i]; ss += ssbuf[i]; }

    const float mean = s * (1.0f / DMODEL);
    const float var  = ss * (1.0f / DMODEL) - mean * mean;
    const float rstd = rsqrtf(var + LN_EPS);

    float4 gv = reinterpret_cast<const float4*>(g)[tid];
    x.x = (x.x - mean) * rstd * gv.x;
    x.y = (x.y - mean) * rstd * gv.y;
    x.z = (x.z - mean) * rstd * gv.z;
    x.w = (x.w - mean) * rstd * gv.w;
    reinterpret_cast<float4*>(p)[tid] = x;
}

// ---------------------------------------------------------------------------
extern "C" void kernel_launch(void* const* d_in, const int* in_sizes, int n_in,
                              void* d_out, int out_size)
{
    const float* q  = (const float*)d_in[0];
    const float* k  = (const float*)d_in[1];
    const float* v  = (const float*)d_in[2];
    const float* W  = (const float*)d_in[3];
    const float* g  = (const float*)d_in[4];
    float* out = (float*)d_out;

    cudaFuncSetAttribute(attn_kernel,
                         cudaFuncAttributeMaxDynamicSharedMemorySize, ATT_SMEM_BYTES);
    cudaFuncSetAttribute(proj_kernel,
                         cudaFuncAttributeMaxDynamicSharedMemorySize, PROJ_SMEM_BYTES);

    prep_qkv<<<(BATCH * SEQ * DMODEL) / 4 / 256, 256>>>(q, k, v);
    prep_w<<<(DMODEL * DMODEL) / 4 / 256, 256>>>(W);

    dim3 agrid(SEQ / BM, BATCH * HEADS);
    attn_kernel<<<agrid, 128, ATT_SMEM_BYTES>>>();

    dim3 pgrid(DMODEL / 64, BATCH * SEQ / 128);
    proj_kernel<<<pgrid, 128, PROJ_SMEM_BYTES>>>(out);

    ln_kernel<<<BATCH * SEQ, 256>>>(out, g);
}